// round 1
// baseline (speedup 1.0000x reference)
#include <cuda_runtime.h>
#include <math.h>

#define D   256
#define NQ  512
#define NK  512
#define D2  512

// ---------------- scratch (static device globals; no allocation) ----------------
__device__ float g_aq[D * NQ];        // (d, n)
__device__ float g_ak[D * NK];        // (d, m)
__device__ float g_prob[NQ * NK];     // (n, m)
__device__ float g_cat[D2 * NQ];      // (c, n): rows 0..255 = x, 256..511 = message
__device__ float g_h2[D2 * NQ];      // (o, n)

// ---------------- generic 32x32-tile SGEMM core ----------------
// out[o0+0..31][n0+0..31] = act( sum_k W[o][k] * X[k][n] + bias[o] )
// XT=false: X[k][n] = Xp[k*ldx + n]   (row-major k x n)
// XT=true : X[k][n] = Xp[n*ldx + k]   (row-major n x k, i.e. C = W * Xp^T)
// 128 threads; each thread computes 2 (o) x 4 (n, float4) outputs.
template<bool XT>
__device__ __forceinline__ void gemm_core(
    const float* __restrict__ W, const float* __restrict__ Xp,
    const float* __restrict__ bias, float* __restrict__ out,
    int K, int ldw, int ldx, int ldo, bool relu)
{
    const int n0  = blockIdx.x * 32;
    const int o0  = blockIdx.y * 32;
    const int tid = threadIdx.x;
    const int nI  = tid & 7;      // float4 column group
    const int oI  = tid >> 3;     // 0..15 -> 2 rows each

    __shared__ float sW[32 * 33]; // [k][o], pad 33 -> conflict-free
    __shared__ float sX[32 * 36]; // [k][n], pad 36 (mult of 4 for float4)

    float4 acc0 = make_float4(0.f, 0.f, 0.f, 0.f);
    float4 acc1 = make_float4(0.f, 0.f, 0.f, 0.f);

    for (int k0 = 0; k0 < K; k0 += 32) {
        __syncthreads();
        {   // load W tile: 32o x 32k, coalesced over k
            const int lk = tid & 31, lo = tid >> 5;
            #pragma unroll
            for (int p = 0; p < 8; p++) {
                int o = lo + p * 4;
                sW[lk * 33 + o] = W[(o0 + o) * ldw + k0 + lk];
            }
        }
        if (!XT) {  // load X tile: 32k x 32n, coalesced over n
            const int ln = tid & 31, lk = tid >> 5;
            #pragma unroll
            for (int p = 0; p < 8; p++) {
                int k = lk + p * 4;
                sX[k * 36 + ln] = Xp[(k0 + k) * ldx + n0 + ln];
            }
        } else {    // load X^T tile: coalesced over k
            const int lk = tid & 31, ln = tid >> 5;
            #pragma unroll
            for (int p = 0; p < 8; p++) {
                int n = ln + p * 4;
                sX[lk * 36 + n] = Xp[(n0 + n) * ldx + k0 + lk];
            }
        }
        __syncthreads();
        #pragma unroll
        for (int k = 0; k < 32; k++) {
            float4 xv = *(const float4*)&sX[k * 36 + nI * 4];
            float w0 = sW[k * 33 + oI * 2];
            float w1 = sW[k * 33 + oI * 2 + 1];
            acc0.x += w0 * xv.x; acc0.y += w0 * xv.y;
            acc0.z += w0 * xv.z; acc0.w += w0 * xv.w;
            acc1.x += w1 * xv.x; acc1.y += w1 * xv.y;
            acc1.z += w1 * xv.z; acc1.w += w1 * xv.w;
        }
    }

    const int oa = o0 + oI * 2, ob = oa + 1;
    float b0 = bias ? bias[oa] : 0.f;
    float b1 = bias ? bias[ob] : 0.f;
    acc0.x += b0; acc0.y += b0; acc0.z += b0; acc0.w += b0;
    acc1.x += b1; acc1.y += b1; acc1.z += b1; acc1.w += b1;
    if (relu) {
        acc0.x = fmaxf(acc0.x, 0.f); acc0.y = fmaxf(acc0.y, 0.f);
        acc0.z = fmaxf(acc0.z, 0.f); acc0.w = fmaxf(acc0.w, 0.f);
        acc1.x = fmaxf(acc1.x, 0.f); acc1.y = fmaxf(acc1.y, 0.f);
        acc1.z = fmaxf(acc1.z, 0.f); acc1.w = fmaxf(acc1.w, 0.f);
    }
    *(float4*)&out[oa * ldo + n0 + nI * 4] = acc0;
    *(float4*)&out[ob * ldo + n0 + nI * 4] = acc1;
}

// ---------------- stage kernels ----------------

// aq = w1[:, :D] @ q + b1 ; ak = w1[:, D:] @ k   (z selects)
__global__ void k_qk(const float* __restrict__ w1, const float* __restrict__ x,
                     const float* __restrict__ src, const float* __restrict__ b1)
{
    if (blockIdx.z == 0)
        gemm_core<false>(w1, x, b1, g_aq, D, 2 * D, NQ, NQ, false);
    else
        gemm_core<false>(w1 + D, src, nullptr, g_ak, D, 2 * D, NK, NK, false);
}

// scores[n][m] = sum_d w2[d] * relu(aq[d][n] + ak[d][m]) + b2
__global__ void k_score(const float* __restrict__ w2, const float* __restrict__ b2,
                        float* __restrict__ scores)
{
    const int m0  = blockIdx.x * 32;
    const int n0  = blockIdx.y * 32;
    const int tid = threadIdx.x;  // 128
    const int mI  = tid & 7;      // float4 over m
    const int nI  = tid >> 3;     // 0..15 -> 2 n rows

    __shared__ float sA[32 * 32]; // [d][n]
    __shared__ float sB[32 * 32]; // [d][m]
    __shared__ float sw[32];

    float4 acc0 = make_float4(0.f, 0.f, 0.f, 0.f);
    float4 acc1 = make_float4(0.f, 0.f, 0.f, 0.f);

    const int lc = tid & 31, lr = tid >> 5;
    for (int d0 = 0; d0 < D; d0 += 32) {
        __syncthreads();
        #pragma unroll
        for (int p = 0; p < 8; p++) {
            int r = lr + p * 4;
            sA[r * 32 + lc] = g_aq[(d0 + r) * NQ + n0 + lc];
            sB[r * 32 + lc] = g_ak[(d0 + r) * NK + m0 + lc];
        }
        if (tid < 32) sw[tid] = w2[d0 + tid];
        __syncthreads();
        #pragma unroll
        for (int k = 0; k < 32; k++) {
            float4 bv = *(const float4*)&sB[k * 32 + mI * 4];
            float a0 = sA[k * 32 + nI * 2];
            float a1 = sA[k * 32 + nI * 2 + 1];
            float w  = sw[k];
            acc0.x += w * fmaxf(a0 + bv.x, 0.f);
            acc0.y += w * fmaxf(a0 + bv.y, 0.f);
            acc0.z += w * fmaxf(a0 + bv.z, 0.f);
            acc0.w += w * fmaxf(a0 + bv.w, 0.f);
            acc1.x += w * fmaxf(a1 + bv.x, 0.f);
            acc1.y += w * fmaxf(a1 + bv.y, 0.f);
            acc1.z += w * fmaxf(a1 + bv.z, 0.f);
            acc1.w += w * fmaxf(a1 + bv.w, 0.f);
        }
    }
    const float bs = b2[0];
    acc0.x += bs; acc0.y += bs; acc0.z += bs; acc0.w += bs;
    acc1.x += bs; acc1.y += bs; acc1.z += bs; acc1.w += bs;
    const int na = n0 + nI * 2;
    *(float4*)&scores[na * NK + m0 + mI * 4]       = acc0;
    *(float4*)&scores[(na + 1) * NK + m0 + mI * 4] = acc1;
}

// row softmax over m; reads raw scores (with bias), writes g_prob
__global__ void k_softmax(const float* __restrict__ scores)
{
    const int n   = blockIdx.x;
    const int tid = threadIdx.x;  // 256
    const float* r = scores + n * NK;
    float a = r[tid], b = r[tid + 256];

    __shared__ float sred[8];
    float mx = fmaxf(a, b);
    #pragma unroll
    for (int o = 16; o; o >>= 1) mx = fmaxf(mx, __shfl_xor_sync(0xffffffffu, mx, o));
    if ((tid & 31) == 0) sred[tid >> 5] = mx;
    __syncthreads();
    float m = sred[0];
    #pragma unroll
    for (int i = 1; i < 8; i++) m = fmaxf(m, sred[i]);

    float ea = expf(a - m), eb = expf(b - m);
    float s = ea + eb;
    __syncthreads();
    #pragma unroll
    for (int o = 16; o; o >>= 1) s += __shfl_xor_sync(0xffffffffu, s, o);
    if ((tid & 31) == 0) sred[tid >> 5] = s;
    __syncthreads();
    float tot = 0.f;
    #pragma unroll
    for (int i = 0; i < 8; i++) tot += sred[i];
    float inv = 1.f / tot;
    g_prob[n * NK + tid]       = ea * inv;
    g_prob[n * NK + tid + 256] = eb * inv;
}

// message[d][n] = sum_m source[d][m] * prob[n][m]  -> cat rows D..2D-1
__global__ void k_msg(const float* __restrict__ src)
{
    gemm_core<true>(src, g_prob, nullptr, g_cat + D * NQ, NK, NK, NK, NQ, false);
}

// h2 = relu(wa @ cat + ba)
__global__ void k_h2(const float* __restrict__ wa, const float* __restrict__ ba)
{
    gemm_core<false>(wa, g_cat, ba, g_h2, D2, D2, NQ, NQ, true);
}

// y = wb @ h2 + bb
__global__ void k_y(const float* __restrict__ wb, const float* __restrict__ bb,
                    float* __restrict__ y)
{
    gemm_core<false>(wb, g_h2, bb, y, D2, D2, NQ, NQ, false);
}

// ---------------- launch ----------------
extern "C" void kernel_launch(void* const* d_in, const int* in_sizes, int n_in,
                              void* d_out, int out_size)
{
    const float* x   = (const float*)d_in[0];
    const float* src = (const float*)d_in[1];
    const float* w1  = (const float*)d_in[2];
    const float* b1  = (const float*)d_in[3];
    const float* w2  = (const float*)d_in[4];
    const float* b2  = (const float*)d_in[5];
    const float* wa  = (const float*)d_in[6];
    const float* ba  = (const float*)d_in[7];
    const float* wb  = (const float*)d_in[8];
    const float* bb  = (const float*)d_in[9];

    float* y      = (float*)d_out;            // (1, D, NQ)  = 131072 floats
    float* scores = y + D * NQ;               // (1, NQ, NK) = 262144 floats

    // cat rows 0..D-1 = x (independent of everything; issue first)
    cudaMemcpyToSymbolAsync(g_cat, x, (size_t)D * NQ * sizeof(float), 0,
                            cudaMemcpyDeviceToDevice, 0);

    k_qk     <<<dim3(NQ / 32, D / 32, 2), 128>>>(w1, x, src, b1);
    k_score  <<<dim3(NK / 32, NQ / 32),    128>>>(w2, b2, scores);
    k_softmax<<<NQ, 256>>>(scores);
    k_msg    <<<dim3(NQ / 32, D / 32),     128>>>(src);
    k_h2     <<<dim3(NQ / 32, D2 / 32),    128>>>(wa, ba);
    k_y      <<<dim3(NQ / 32, D / 32),     128>>>(wb, bb, y);
}